// round 16
// baseline (speedup 1.0000x reference)
#include <cuda_runtime.h>
#include <cuda_fp16.h>
#include <math.h>
#include <stdint.h>

#define B_SZ  2
#define S_LEN 2048
#define D_DIM 1024
#define H_NUM 16
#define DKH   64
#define MTOT  (B_SZ * S_LEN)          // 4096

// ---------------------------------------------------------------------------
// Scratch (allocation-free rule: __device__ globals). fp16 intermediates.
// ---------------------------------------------------------------------------
__device__ __half g_Qv[MTOT * D_DIM], g_Kv[MTOT * D_DIM], g_Vv[MTOT * D_DIM];
__device__ __half g_Xv[MTOT * D_DIM];

// ===========================================================================
// helpers
// ===========================================================================
__device__ __forceinline__ uint32_t smem_u32(const void* p) {
    uint32_t a;
    asm("{ .reg .u64 t; cvta.to.shared.u64 t, %1; cvt.u32.u64 %0, t; }"
        : "=r"(a) : "l"(p));
    return a;
}
__device__ __forceinline__ void ldmx4(uint32_t* r, uint32_t addr) {
    asm volatile("ldmatrix.sync.aligned.m8n8.x4.shared.b16 {%0,%1,%2,%3}, [%4];"
                 : "=r"(r[0]), "=r"(r[1]), "=r"(r[2]), "=r"(r[3]) : "r"(addr));
}
__device__ __forceinline__ void ldmx4t(uint32_t* r, uint32_t addr) {
    asm volatile("ldmatrix.sync.aligned.m8n8.x4.trans.shared.b16 {%0,%1,%2,%3}, [%4];"
                 : "=r"(r[0]), "=r"(r[1]), "=r"(r[2]), "=r"(r[3]) : "r"(addr));
}
__device__ __forceinline__ void mma16816(float* c, const uint32_t* a,
                                         uint32_t b0, uint32_t b1) {
    asm("mma.sync.aligned.m16n8k16.row.col.f32.f16.f16.f32 "
        "{%0,%1,%2,%3}, {%4,%5,%6,%7}, {%8,%9}, {%0,%1,%2,%3};"
        : "+f"(c[0]), "+f"(c[1]), "+f"(c[2]), "+f"(c[3])
        : "r"(a[0]), "r"(a[1]), "r"(a[2]), "r"(a[3]), "r"(b0), "r"(b1));
}
__device__ __forceinline__ uint32_t packh(float x, float y) {
    __half2 h = __float22half2_rn(make_float2(x, y));
    return *(uint32_t*)&h;
}
__device__ __forceinline__ void cpasync16(uint32_t dst, const void* src) {
    asm volatile("cp.async.cg.shared.global [%0], [%1], 16;"
                 :: "r"(dst), "l"(src));
}
__device__ __forceinline__ void cp_commit() {
    asm volatile("cp.async.commit_group;" ::: "memory");
}
__device__ __forceinline__ void cp_wait0() {
    asm volatile("cp.async.wait_group 0;" ::: "memory");
}
__device__ __forceinline__ void cp_wait1() {
    asm volatile("cp.async.wait_group 1;" ::: "memory");
}

// ===========================================================================
// GEMM geometry: CTA tile 128x128, 256 threads = 8 warps (2m x 4n),
// warp tile 64x32 (acc 4x4 m16n8). Single-buffered serial producer that
// converts f32 -> fp16 in registers. 2 CTAs/SM hide the producer phase.
// ===========================================================================
constexpr int SASB   = 144;                // padded row bytes (64 fp16 + pad)
constexpr int GT     = 128 * SASB;         // 18432 per 128-row tile
constexpr int SM_GEMM_TOTAL = 2 * GT;      // 36864 (x2 CTAs = 72KB/SM)
constexpr int STAGES = D_DIM / 64;         // 16

__device__ __forceinline__ void gemm_stage_compute(
    uint32_t sb, int warp_m, int warp_n, int lr, int lkb, float acc[4][4][4])
{
#pragma unroll
    for (int ks = 0; ks < 4; ks++) {
        const uint32_t kb = ks * 32 + lkb;
        uint32_t ah[4][4];
#pragma unroll
        for (int mi = 0; mi < 4; mi++) {
            const uint32_t byte = (warp_m * 64 + mi * 16 + lr) * SASB + kb;
            ldmx4(ah[mi], sb + byte);
        }
        uint32_t bh[4][2];
#pragma unroll
        for (int nb = 0; nb < 2; nb++) {
            const uint32_t byte = (warp_n * 32 + nb * 16 + lr) * SASB + kb;
            uint32_t r[4];
            ldmx4(r, sb + GT + byte);
            bh[nb * 2][0] = r[0]; bh[nb * 2 + 1][0] = r[1];
            bh[nb * 2][1] = r[2]; bh[nb * 2 + 1][1] = r[3];
        }
#pragma unroll
        for (int mi = 0; mi < 4; mi++)
#pragma unroll
            for (int ni = 0; ni < 4; ni++)
                mma16816(acc[mi][ni], ah[mi], bh[ni][0], bh[ni][1]);
    }
}

// ===========================================================================
// gemm_proj: z=0/1/2 -> Q/K/V. f32 inputs converted in-producer, fp16 out.
// ===========================================================================
__global__ __launch_bounds__(256, 2)
void gemm_proj(const float* __restrict__ Aq, const float* __restrict__ Ak,
               const float* __restrict__ Av,
               const float* __restrict__ Wq, const float* __restrict__ Wk,
               const float* __restrict__ Wv,
               __half* __restrict__ Qv, __half* __restrict__ Kv,
               __half* __restrict__ Vv)
{
    extern __shared__ char smc[];
    const uint32_t sb = smem_u32(smc);
    const int tid  = threadIdx.x;
    const int wid  = tid >> 5;
    const int lane = tid & 31;
    const int warp_m = wid & 1;
    const int warp_n = wid >> 1;
    const int m0 = blockIdx.y * 128;
    const int n0 = blockIdx.x * 128;
    const int z  = blockIdx.z;
    const int K  = D_DIM, N = D_DIM;

    const float* Ab = ((z == 0) ? Aq : (z == 1) ? Ak : Av) + (size_t)m0 * K;
    const float* Wb = ((z == 0) ? Wq : (z == 1) ? Wk : Wv) + (size_t)n0 * K;

    float acc[4][4][4];
#pragma unroll
    for (int mi = 0; mi < 4; mi++)
#pragma unroll
        for (int ni = 0; ni < 4; ni++)
#pragma unroll
            for (int q = 0; q < 4; q++) acc[mi][ni][q] = 0.f;

    const int lr  = lane & 15;
    const int lkb = (lane >> 4) << 4;
    const int prow = tid >> 4;    // load mapping helpers
    const int pch  = tid & 15;

    for (int s = 0; s < STAGES; s++) {
        __syncthreads();   // prior compute done with the buffer
        // ---- serial producer: f32 load -> fp16 convert -> STS ----
#pragma unroll
        for (int i = 0; i < 8; i++) {
            const int row = (i << 4) | prow;       // 0..127
            const float4 va = *(const float4*)(Ab + (size_t)row * K + s * 64 + pch * 4);
            const float4 vw = *(const float4*)(Wb + (size_t)row * K + s * 64 + pch * 4);
            const uint32_t off = row * SASB + pch * 8;
            *(uint2*)(smc + off)      = make_uint2(packh(va.x, va.y), packh(va.z, va.w));
            *(uint2*)(smc + GT + off) = make_uint2(packh(vw.x, vw.y), packh(vw.z, vw.w));
        }
        __syncthreads();
        gemm_stage_compute(sb, warp_m, warp_n, lr, lkb, acc);
    }

    const int er = lane >> 2;
    const int ec = (lane & 3) * 2;
    __half* C = (z == 0) ? Qv : (z == 1) ? Kv : Vv;
#pragma unroll
    for (int mi = 0; mi < 4; mi++)
#pragma unroll
        for (int ni = 0; ni < 4; ni++) {
            const int r = m0 + warp_m * 64 + mi * 16 + er;
            const int c = n0 + warp_n * 32 + ni * 8 + ec;
            *(uint32_t*)(C + (size_t)r * N + c) =
                packh(acc[mi][ni][0], acc[mi][ni][1]);
            *(uint32_t*)(C + (size_t)(r + 8) * N + c) =
                packh(acc[mi][ni][2], acc[mi][ni][3]);
        }
}

// ===========================================================================
// gemm_out: out = X @ Wo^T (f32 out). X fp16 (copied), Wo f32 (converted).
// ===========================================================================
__global__ __launch_bounds__(256, 2)
void gemm_out(const __half* __restrict__ Xv, const float* __restrict__ Wo,
              float* __restrict__ out)
{
    extern __shared__ char smc[];
    const uint32_t sb = smem_u32(smc);
    const int tid  = threadIdx.x;
    const int wid  = tid >> 5;
    const int lane = tid & 31;
    const int warp_m = wid & 1;
    const int warp_n = wid >> 1;
    const int m0 = blockIdx.y * 128;
    const int n0 = blockIdx.x * 128;
    const int K  = D_DIM, N = D_DIM;

    const __half* Ab = Xv + (size_t)m0 * K;
    const float*  Wb = Wo + (size_t)n0 * K;

    float acc[4][4][4];
#pragma unroll
    for (int mi = 0; mi < 4; mi++)
#pragma unroll
        for (int ni = 0; ni < 4; ni++)
#pragma unroll
            for (int q = 0; q < 4; q++) acc[mi][ni][q] = 0.f;

    const int lr  = lane & 15;
    const int lkb = (lane >> 4) << 4;
    const int prow = tid >> 4;
    const int pch  = tid & 15;
    const int xrow = tid >> 3;    // X copy mapping (16B chunks)
    const int xch  = tid & 7;

    for (int s = 0; s < STAGES; s++) {
        __syncthreads();
        // ---- X: straight fp16 16B copies (4 per thread) ----
#pragma unroll
        for (int i = 0; i < 4; i++) {
            const int row = (i << 5) | xrow;       // 0..127
            const uint4 v = *(const uint4*)(Ab + (size_t)row * K + s * 64 + xch * 8);
            *(uint4*)(smc + row * SASB + xch * 16) = v;
        }
        // ---- Wo: f32 load -> fp16 convert -> STS (8 per thread) ----
#pragma unroll
        for (int i = 0; i < 8; i++) {
            const int row = (i << 4) | prow;
            const float4 vw = *(const float4*)(Wb + (size_t)row * K + s * 64 + pch * 4);
            *(uint2*)(smc + GT + row * SASB + pch * 8) =
                make_uint2(packh(vw.x, vw.y), packh(vw.z, vw.w));
        }
        __syncthreads();
        gemm_stage_compute(sb, warp_m, warp_n, lr, lkb, acc);
    }

    const int er = lane >> 2;
    const int ec = (lane & 3) * 2;
#pragma unroll
    for (int mi = 0; mi < 4; mi++)
#pragma unroll
        for (int ni = 0; ni < 4; ni++) {
            const int r = m0 + warp_m * 64 + mi * 16 + er;
            const int c = n0 + warp_n * 32 + ni * 8 + ec;
            *(float2*)(out + (size_t)r * N + c) =
                make_float2(acc[mi][ni][0], acc[mi][ni][1]);
            *(float2*)(out + (size_t)(r + 8) * N + c) =
                make_float2(acc[mi][ni][2], acc[mi][ni][3]);
        }
}

// ===========================================================================
// Flash attention (causal). CTA = 128 q-rows x (b,h), 256 threads, 8 warps.
// Q, K, V, P single fp16; single fp16 X output. 2 CTAs/SM.
// (byte-identical to the 256.8us Round-15 version)
// ===========================================================================
constexpr int FQT  = 128 * SASB;           // 18432: single Q tile
constexpr int FKV0 = FQT;                  // 18432
constexpr int KVT  = 64 * SASB;            // 9216 per 64-row tile
constexpr int KVBUF = 2 * KVT;             // 18432 (K, V)
constexpr int FSM_TOTAL = FKV0 + 2 * KVBUF;  // 55296 (x2 CTAs = 108KB/SM)

__global__ __launch_bounds__(256, 2)
void flash_mma(const __half* __restrict__ Qv, const __half* __restrict__ Kv,
               const __half* __restrict__ Vv, __half* __restrict__ Xv)
{
    extern __shared__ char smc[];
    const uint32_t sb = smem_u32(smc);
    const int tid  = threadIdx.x;
    const int wid  = tid >> 5;
    const int lane = tid & 31;
    const int qb   = gridDim.x - 1 - blockIdx.x;   // longest blocks first
    const int h    = blockIdx.y;
    const int b    = blockIdx.z;

    const size_t head = (size_t)b * S_LEN * D_DIM + (size_t)h * DKH;
    const int prow = tid >> 3;
    const int pch  = tid & 7;

    { // Q tile (single): 4 cp.async per thread
#pragma unroll
        for (int i = 0; i < 4; i++) {
            const int row = (i << 5) | prow;
            const void* src = Qv + head + (size_t)(qb * 128 + row) * D_DIM + pch * 8;
            cpasync16(sb + row * SASB + pch * 16, src);
        }
    }

    const __half* kvb[2] = {Kv + head, Vv + head};
    auto produce_kv = [&](int kb) {
        const uint32_t bufb = sb + FKV0 + (kb & 1) * KVBUF;
#pragma unroll
        for (int i = 0; i < 4; i++) {
            const int t   = i >> 1;
            const int row = ((i & 1) << 5) | prow;
            const void* src = kvb[t] + (size_t)(kb * 64 + row) * D_DIM + pch * 8;
            cpasync16(bufb + t * KVT + row * SASB + pch * 16, src);
        }
    };

    produce_kv(0);
    cp_commit();

    float o[8][4];
    float m0r = -1e30f, m1r = -1e30f, l0r = 0.f, l1r = 0.f;
#pragma unroll
    for (int ni = 0; ni < 8; ni++)
#pragma unroll
        for (int q = 0; q < 4; q++) o[ni][q] = 0.f;

    const int lr  = lane & 15;
    const int lkb = (lane >> 4) << 4;
    const int kb_max = 2 * qb + 1;

    for (int kb = 0; kb <= kb_max; kb++) {
        if (kb < kb_max) {
            produce_kv(kb + 1);
            cp_commit();
            cp_wait1();
        } else {
            cp_wait0();
        }
        __syncthreads();

        const uint32_t kvbase = sb + FKV0 + (kb & 1) * KVBUF;

        // ---- QK^T ----
        float sc[8][4];
#pragma unroll
        for (int ni = 0; ni < 8; ni++)
#pragma unroll
            for (int q = 0; q < 4; q++) sc[ni][q] = 0.f;

#pragma unroll
        for (int ks = 0; ks < 4; ks++) {
            const uint32_t abyte = (wid * 16 + lr) * SASB + ks * 32 + lkb;
            uint32_t qh[4];
            ldmx4(qh, sb + abyte);
#pragma unroll
            for (int nb = 0; nb < 4; nb++) {
                const uint32_t bbyte = (nb * 16 + lr) * SASB + ks * 32 + lkb;
                uint32_t kh[4];
                ldmx4(kh, kvbase + bbyte);
                mma16816(sc[nb * 2],     qh, kh[0], kh[2]);
                mma16816(sc[nb * 2 + 1], qh, kh[1], kh[3]);
            }
        }

#pragma unroll
        for (int ni = 0; ni < 8; ni++)
#pragma unroll
            for (int q = 0; q < 4; q++) sc[ni][q] *= 0.125f;

        const int q0 = qb * 128 + wid * 16 + (lane >> 2);
        if (kb * 64 + 63 > qb * 128 + wid * 16) {
#pragma unroll
            for (int ni = 0; ni < 8; ni++) {
#pragma unroll
                for (int c = 0; c < 2; c++) {
                    const int col = kb * 64 + ni * 8 + (lane & 3) * 2 + c;
                    if (col > q0)     sc[ni][c]     = -1e30f;
                    if (col > q0 + 8) sc[ni][2 + c] = -1e30f;
                }
            }
        }

        float mx0 = -1e30f, mx1 = -1e30f;
#pragma unroll
        for (int ni = 0; ni < 8; ni++) {
            mx0 = fmaxf(mx0, fmaxf(sc[ni][0], sc[ni][1]));
            mx1 = fmaxf(mx1, fmaxf(sc[ni][2], sc[ni][3]));
        }
        mx0 = fmaxf(mx0, __shfl_xor_sync(0xffffffffu, mx0, 1));
        mx0 = fmaxf(mx0, __shfl_xor_sync(0xffffffffu, mx0, 2));
        mx1 = fmaxf(mx1, __shfl_xor_sync(0xffffffffu, mx1, 1));
        mx1 = fmaxf(mx1, __shfl_xor_sync(0xffffffffu, mx1, 2));

        const float mn0 = fmaxf(m0r, mx0);
        const float mn1 = fmaxf(m1r, mx1);
        const float al0 = __expf(m0r - mn0);
        const float al1 = __expf(m1r - mn1);
        m0r = mn0; m1r = mn1;

        float ls0 = 0.f, ls1 = 0.f;
#pragma unroll
        for (int ni = 0; ni < 8; ni++) {
            sc[ni][0] = __expf(sc[ni][0] - mn0); ls0 += sc[ni][0];
            sc[ni][1] = __expf(sc[ni][1] - mn0); ls0 += sc[ni][1];
            sc[ni][2] = __expf(sc[ni][2] - mn1); ls1 += sc[ni][2];
            sc[ni][3] = __expf(sc[ni][3] - mn1); ls1 += sc[ni][3];
        }
        ls0 += __shfl_xor_sync(0xffffffffu, ls0, 1);
        ls0 += __shfl_xor_sync(0xffffffffu, ls0, 2);
        ls1 += __shfl_xor_sync(0xffffffffu, ls1, 1);
        ls1 += __shfl_xor_sync(0xffffffffu, ls1, 2);
        l0r = l0r * al0 + ls0;
        l1r = l1r * al1 + ls1;
#pragma unroll
        for (int ni = 0; ni < 8; ni++) {
            o[ni][0] *= al0; o[ni][1] *= al0;
            o[ni][2] *= al1; o[ni][3] *= al1;
        }

        // ---- P.V ----
#pragma unroll
        for (int ks = 0; ks < 4; ks++) {
            uint32_t ph[4];
            ph[0] = packh(sc[2 * ks][0],     sc[2 * ks][1]);
            ph[1] = packh(sc[2 * ks][2],     sc[2 * ks][3]);
            ph[2] = packh(sc[2 * ks + 1][0], sc[2 * ks + 1][1]);
            ph[3] = packh(sc[2 * ks + 1][2], sc[2 * ks + 1][3]);
#pragma unroll
            for (int nt = 0; nt < 4; nt++) {
                const uint32_t vbyte =
                    (ks * 16 + ((lane >> 3) & 1) * 8 + (lane & 7)) * SASB +
                    nt * 32 + ((lane >> 4) << 4);
                uint32_t vh[4];
                ldmx4t(vh, kvbase + KVT + vbyte);
                mma16816(o[nt * 2],     ph, vh[0], vh[1]);
                mma16816(o[nt * 2 + 1], ph, vh[2], vh[3]);
            }
        }
        __syncthreads();
    }

    const float inv0 = 1.f / l0r;
    const float inv1 = 1.f / l1r;
    const int r0 = qb * 128 + wid * 16 + (lane >> 2);
    const int ec = (lane & 3) * 2;
#pragma unroll
    for (int ni = 0; ni < 8; ni++) {
        const size_t c = head + (size_t)ni * 8 + ec;
        *(uint32_t*)(Xv + c + (size_t)r0 * D_DIM) =
            packh(o[ni][0] * inv0, o[ni][1] * inv0);
        *(uint32_t*)(Xv + c + (size_t)(r0 + 8) * D_DIM) =
            packh(o[ni][2] * inv1, o[ni][3] * inv1);
    }
}

// ---------------------------------------------------------------------------
// launch
// ---------------------------------------------------------------------------
extern "C" void kernel_launch(void* const* d_in, const int* in_sizes, int n_in,
                              void* d_out, int out_size)
{
    const float* query = (const float*)d_in[0];
    const float* key   = (const float*)d_in[1];
    const float* value = (const float*)d_in[2];
    const float* Wq    = (const float*)d_in[3];
    const float* Wk    = (const float*)d_in[4];
    const float* Wv    = (const float*)d_in[5];
    const float* Wo    = (const float*)d_in[6];
    float* out = (float*)d_out;

    __half *Qv, *Kv, *Vv, *Xv;
    cudaGetSymbolAddress((void**)&Qv, g_Qv); cudaGetSymbolAddress((void**)&Kv, g_Kv);
    cudaGetSymbolAddress((void**)&Vv, g_Vv); cudaGetSymbolAddress((void**)&Xv, g_Xv);

    cudaFuncSetAttribute(gemm_proj, cudaFuncAttributeMaxDynamicSharedMemorySize,
                         SM_GEMM_TOTAL);
    cudaFuncSetAttribute(gemm_out, cudaFuncAttributeMaxDynamicSharedMemorySize,
                         SM_GEMM_TOTAL);
    cudaFuncSetAttribute(flash_mma, cudaFuncAttributeMaxDynamicSharedMemorySize,
                         FSM_TOTAL);

    dim3 pgrid(D_DIM / 128, MTOT / 128, 3);   // (8, 32, 3)
    gemm_proj<<<pgrid, 256, SM_GEMM_TOTAL>>>(query, key, value, Wq, Wk, Wv,
                                             Qv, Kv, Vv);

    dim3 fgrid(S_LEN / 128, H_NUM, B_SZ);     // (16, 16, 2)
    flash_mma<<<fgrid, 256, FSM_TOTAL>>>(Qv, Kv, Vv, Xv);

    dim3 ogrid(D_DIM / 128, MTOT / 128);      // (8, 32)
    gemm_out<<<ogrid, 256, SM_GEMM_TOTAL>>>(Xv, Wo, out);
}

// round 17
// speedup vs baseline: 1.0581x; 1.0581x over previous
#include <cuda_runtime.h>
#include <cuda_fp16.h>
#include <math.h>
#include <stdint.h>

#define B_SZ  2
#define S_LEN 2048
#define D_DIM 1024
#define H_NUM 16
#define DKH   64
#define MTOT  (B_SZ * S_LEN)          // 4096

// ---------------------------------------------------------------------------
// Scratch (allocation-free rule: __device__ globals). All single fp16.
// ---------------------------------------------------------------------------
__device__ __half g_aQ[MTOT * D_DIM], g_aK[MTOT * D_DIM], g_aV[MTOT * D_DIM];
__device__ __half g_wq[D_DIM * D_DIM], g_wk[D_DIM * D_DIM];
__device__ __half g_wv[D_DIM * D_DIM], g_wo[D_DIM * D_DIM];
__device__ __half g_Qv[MTOT * D_DIM], g_Kv[MTOT * D_DIM], g_Vv[MTOT * D_DIM];
__device__ __half g_Xv[MTOT * D_DIM];

// ===========================================================================
// helpers
// ===========================================================================
__device__ __forceinline__ uint32_t smem_u32(const void* p) {
    uint32_t a;
    asm("{ .reg .u64 t; cvta.to.shared.u64 t, %1; cvt.u32.u64 %0, t; }"
        : "=r"(a) : "l"(p));
    return a;
}
__device__ __forceinline__ void ldmx4(uint32_t* r, uint32_t addr) {
    asm volatile("ldmatrix.sync.aligned.m8n8.x4.shared.b16 {%0,%1,%2,%3}, [%4];"
                 : "=r"(r[0]), "=r"(r[1]), "=r"(r[2]), "=r"(r[3]) : "r"(addr));
}
__device__ __forceinline__ void ldmx4t(uint32_t* r, uint32_t addr) {
    asm volatile("ldmatrix.sync.aligned.m8n8.x4.trans.shared.b16 {%0,%1,%2,%3}, [%4];"
                 : "=r"(r[0]), "=r"(r[1]), "=r"(r[2]), "=r"(r[3]) : "r"(addr));
}
__device__ __forceinline__ void mma16816(float* c, const uint32_t* a,
                                         uint32_t b0, uint32_t b1) {
    asm("mma.sync.aligned.m16n8k16.row.col.f32.f16.f16.f32 "
        "{%0,%1,%2,%3}, {%4,%5,%6,%7}, {%8,%9}, {%0,%1,%2,%3};"
        : "+f"(c[0]), "+f"(c[1]), "+f"(c[2]), "+f"(c[3])
        : "r"(a[0]), "r"(a[1]), "r"(a[2]), "r"(a[3]), "r"(b0), "r"(b1));
}
__device__ __forceinline__ uint32_t packh(float x, float y) {
    __half2 h = __float22half2_rn(make_float2(x, y));
    return *(uint32_t*)&h;
}
__device__ __forceinline__ void cpasync16(uint32_t dst, const void* src) {
    asm volatile("cp.async.cg.shared.global [%0], [%1], 16;"
                 :: "r"(dst), "l"(src));
}
__device__ __forceinline__ void cp_commit() {
    asm volatile("cp.async.commit_group;" ::: "memory");
}
__device__ __forceinline__ void cp_wait0() {
    asm volatile("cp.async.wait_group 0;" ::: "memory");
}
__device__ __forceinline__ void cp_wait1() {
    asm volatile("cp.async.wait_group 1;" ::: "memory");
}

// ===========================================================================
// convert_all: z=0..6 -> single fp16 convert of q,k,v,Wq,Wk,Wv,Wo
// ===========================================================================
__global__ void convert_all(const float4* __restrict__ q, const float4* __restrict__ k,
                            const float4* __restrict__ v,
                            const float4* __restrict__ wq, const float4* __restrict__ wk,
                            const float4* __restrict__ wv, const float4* __restrict__ wo,
                            uint2* __restrict__ oq, uint2* __restrict__ ok,
                            uint2* __restrict__ ov,
                            uint2* __restrict__ owq, uint2* __restrict__ owk,
                            uint2* __restrict__ owv, uint2* __restrict__ owo)
{
    const int z = blockIdx.z;
    const int stride = gridDim.x * blockDim.x;
    const float4* src = (z == 0) ? q : (z == 1) ? k : (z == 2) ? v :
                        (z == 3) ? wq : (z == 4) ? wk : (z == 5) ? wv : wo;
    uint2* dst = (z == 0) ? oq : (z == 1) ? ok : (z == 2) ? ov :
                 (z == 3) ? owq : (z == 4) ? owk : (z == 5) ? owv : owo;
    const int n4 = ((z < 3) ? MTOT * D_DIM : D_DIM * D_DIM) / 4;
    for (int i = blockIdx.x * blockDim.x + threadIdx.x; i < n4; i += stride) {
        const float4 w = src[i];
        dst[i] = make_uint2(packh(w.x, w.y), packh(w.z, w.w));
    }
}

// ===========================================================================
// GEMM geometry: CTA tile 128x128, 256 threads = 8 warps (2m x 4n),
// warp tile 64x32 (acc 4x4 m16n8). Single fp16 operands.
// 3-stage cp.async ring -> ONE __syncthreads per stage. 2 CTAs/SM.
// ===========================================================================
constexpr int SASB   = 144;                // padded row bytes (64 fp16 + pad)
constexpr int GT     = 128 * SASB;         // 18432 per 128-row tile
constexpr int GSTAGE = 2 * GT;             // 36864 per stage (A, B)
constexpr int NSTG   = 3;
constexpr int SM_GEMM_TOTAL = NSTG * GSTAGE;  // 110592 (x2 CTAs = 216KB/SM)
constexpr int STAGES = D_DIM / 64;         // 16

__device__ __forceinline__ void gemm_stage_compute(
    uint32_t bufb, int warp_m, int warp_n, int lr, int lkb, float acc[4][4][4])
{
#pragma unroll
    for (int ks = 0; ks < 4; ks++) {
        const uint32_t kb = ks * 32 + lkb;
        uint32_t ah[4][4];
#pragma unroll
        for (int mi = 0; mi < 4; mi++) {
            const uint32_t byte = (warp_m * 64 + mi * 16 + lr) * SASB + kb;
            ldmx4(ah[mi], bufb + byte);
        }
        uint32_t bh[4][2];
#pragma unroll
        for (int nb = 0; nb < 2; nb++) {
            const uint32_t byte = (warp_n * 32 + nb * 16 + lr) * SASB + kb;
            uint32_t r[4];
            ldmx4(r, bufb + GT + byte);
            bh[nb * 2][0] = r[0]; bh[nb * 2 + 1][0] = r[1];
            bh[nb * 2][1] = r[2]; bh[nb * 2 + 1][1] = r[3];
        }
#pragma unroll
        for (int mi = 0; mi < 4; mi++)
#pragma unroll
            for (int ni = 0; ni < 4; ni++)
                mma16816(acc[mi][ni], ah[mi], bh[ni][0], bh[ni][1]);
    }
}

// producer: 8 cp.async per thread per stage (2 tiles x 1024 16B-chunks)
__device__ __forceinline__ void gemm_produce(
    uint32_t sb, int s, const __half* Ab, const __half* Bb, int tid)
{
    const uint32_t bufb = sb + (s % NSTG) * GSTAGE;
#pragma unroll
    for (int i = 0; i < 8; i++) {
        const int c = i * 256 + tid;          // 0..2047
        const int t = c >> 10;                // tile 0..1
        const int w = c & 1023;
        const int row = w >> 3, ch = w & 7;
        const __half* src = (t == 0) ? Ab : Bb;
        cpasync16(bufb + t * GT + row * SASB + ch * 16,
                  src + (size_t)row * D_DIM + s * 64 + ch * 8);
    }
}

// shared GEMM mainloop (3-stage ring, single barrier per stage)
__device__ __forceinline__ void gemm_mainloop(
    uint32_t sb, const __half* Ab, const __half* Bb, int tid,
    int warp_m, int warp_n, int lr, int lkb, float acc[4][4][4])
{
    gemm_produce(sb, 0, Ab, Bb, tid);
    cp_commit();
    gemm_produce(sb, 1, Ab, Bb, tid);
    cp_commit();

    for (int s = 0; s < STAGES; s++) {
        if (s + 2 < STAGES) cp_wait1(); else if (s + 1 < STAGES) cp_wait1();
        else cp_wait0();
        __syncthreads();
        gemm_stage_compute(sb + (s % NSTG) * GSTAGE, warp_m, warp_n, lr, lkb, acc);
        if (s + 2 < STAGES) {
            gemm_produce(sb, s + 2, Ab, Bb, tid);
            cp_commit();
        }
    }
}

// ===========================================================================
// gemm_proj: z=0/1/2 -> Q/K/V, single fp16 in and out.
// ===========================================================================
__global__ __launch_bounds__(256, 2)
void gemm_proj(const __half* __restrict__ aQ, const __half* __restrict__ aK,
               const __half* __restrict__ aV,
               const __half* __restrict__ wq, const __half* __restrict__ wk,
               const __half* __restrict__ wv,
               __half* __restrict__ Qv, __half* __restrict__ Kv,
               __half* __restrict__ Vv)
{
    extern __shared__ char smc[];
    const uint32_t sb = smem_u32(smc);
    const int tid  = threadIdx.x;
    const int wid  = tid >> 5;
    const int lane = tid & 31;
    const int warp_m = wid & 1;
    const int warp_n = wid >> 1;
    const int m0 = blockIdx.y * 128;
    const int n0 = blockIdx.x * 128;
    const int z  = blockIdx.z;
    const int N  = D_DIM;

    const __half* Ab = ((z == 0) ? aQ : (z == 1) ? aK : aV) + (size_t)m0 * D_DIM;
    const __half* Bb = ((z == 0) ? wq : (z == 1) ? wk : wv) + (size_t)n0 * D_DIM;

    float acc[4][4][4];
#pragma unroll
    for (int mi = 0; mi < 4; mi++)
#pragma unroll
        for (int ni = 0; ni < 4; ni++)
#pragma unroll
            for (int q = 0; q < 4; q++) acc[mi][ni][q] = 0.f;

    const int lr  = lane & 15;
    const int lkb = (lane >> 4) << 4;

    gemm_mainloop(sb, Ab, Bb, tid, warp_m, warp_n, lr, lkb, acc);

    const int er = lane >> 2;
    const int ec = (lane & 3) * 2;
    __half* C = (z == 0) ? Qv : (z == 1) ? Kv : Vv;
#pragma unroll
    for (int mi = 0; mi < 4; mi++)
#pragma unroll
        for (int ni = 0; ni < 4; ni++) {
            const int r = m0 + warp_m * 64 + mi * 16 + er;
            const int c = n0 + warp_n * 32 + ni * 8 + ec;
            *(uint32_t*)(C + (size_t)r * N + c) =
                packh(acc[mi][ni][0], acc[mi][ni][1]);
            *(uint32_t*)(C + (size_t)(r + 8) * N + c) =
                packh(acc[mi][ni][2], acc[mi][ni][3]);
        }
}

// ===========================================================================
// gemm_out: out = X @ Wo^T (f32 out). X and Wo single fp16.
// ===========================================================================
__global__ __launch_bounds__(256, 2)
void gemm_out(const __half* __restrict__ Xv, const __half* __restrict__ wo,
              float* __restrict__ out)
{
    extern __shared__ char smc[];
    const uint32_t sb = smem_u32(smc);
    const int tid  = threadIdx.x;
    const int wid  = tid >> 5;
    const int lane = tid & 31;
    const int warp_m = wid & 1;
    const int warp_n = wid >> 1;
    const int m0 = blockIdx.y * 128;
    const int n0 = blockIdx.x * 128;
    const int N  = D_DIM;

    const __half* Ab = Xv + (size_t)m0 * D_DIM;
    const __half* Bb = wo + (size_t)n0 * D_DIM;

    float acc[4][4][4];
#pragma unroll
    for (int mi = 0; mi < 4; mi++)
#pragma unroll
        for (int ni = 0; ni < 4; ni++)
#pragma unroll
            for (int q = 0; q < 4; q++) acc[mi][ni][q] = 0.f;

    const int lr  = lane & 15;
    const int lkb = (lane >> 4) << 4;

    gemm_mainloop(sb, Ab, Bb, tid, warp_m, warp_n, lr, lkb, acc);

    const int er = lane >> 2;
    const int ec = (lane & 3) * 2;
#pragma unroll
    for (int mi = 0; mi < 4; mi++)
#pragma unroll
        for (int ni = 0; ni < 4; ni++) {
            const int r = m0 + warp_m * 64 + mi * 16 + er;
            const int c = n0 + warp_n * 32 + ni * 8 + ec;
            *(float2*)(out + (size_t)r * N + c) =
                make_float2(acc[mi][ni][0], acc[mi][ni][1]);
            *(float2*)(out + (size_t)(r + 8) * N + c) =
                make_float2(acc[mi][ni][2], acc[mi][ni][3]);
        }
}

// ===========================================================================
// Flash attention (causal). CTA = 128 q-rows x (b,h), 256 threads, 8 warps.
// Q, K, V, P single fp16; single fp16 X output. 2 CTAs/SM.
// (byte-identical to the 256.8us Round-15 version)
// ===========================================================================
constexpr int FQT  = 128 * SASB;           // 18432: single Q tile
constexpr int FKV0 = FQT;                  // 18432
constexpr int KVT  = 64 * SASB;            // 9216 per 64-row tile
constexpr int KVBUF = 2 * KVT;             // 18432 (K, V)
constexpr int FSM_TOTAL = FKV0 + 2 * KVBUF;  // 55296 (x2 CTAs = 108KB/SM)

__global__ __launch_bounds__(256, 2)
void flash_mma(const __half* __restrict__ Qv, const __half* __restrict__ Kv,
               const __half* __restrict__ Vv, __half* __restrict__ Xv)
{
    extern __shared__ char smc[];
    const uint32_t sb = smem_u32(smc);
    const int tid  = threadIdx.x;
    const int wid  = tid >> 5;
    const int lane = tid & 31;
    const int qb   = gridDim.x - 1 - blockIdx.x;   // longest blocks first
    const int h    = blockIdx.y;
    const int b    = blockIdx.z;

    const size_t head = (size_t)b * S_LEN * D_DIM + (size_t)h * DKH;
    const int prow = tid >> 3;
    const int pch  = tid & 7;

    { // Q tile (single): 4 cp.async per thread
#pragma unroll
        for (int i = 0; i < 4; i++) {
            const int row = (i << 5) | prow;
            const void* src = Qv + head + (size_t)(qb * 128 + row) * D_DIM + pch * 8;
            cpasync16(sb + row * SASB + pch * 16, src);
        }
    }

    const __half* kvb[2] = {Kv + head, Vv + head};
    auto produce_kv = [&](int kb) {
        const uint32_t bufb = sb + FKV0 + (kb & 1) * KVBUF;
#pragma unroll
        for (int i = 0; i < 4; i++) {
            const int t   = i >> 1;
            const int row = ((i & 1) << 5) | prow;
            const void* src = kvb[t] + (size_t)(kb * 64 + row) * D_DIM + pch * 8;
            cpasync16(bufb + t * KVT + row * SASB + pch * 16, src);
        }
    };

    produce_kv(0);
    cp_commit();

    float o[8][4];
    float m0r = -1e30f, m1r = -1e30f, l0r = 0.f, l1r = 0.f;
#pragma unroll
    for (int ni = 0; ni < 8; ni++)
#pragma unroll
        for (int q = 0; q < 4; q++) o[ni][q] = 0.f;

    const int lr  = lane & 15;
    const int lkb = (lane >> 4) << 4;
    const int kb_max = 2 * qb + 1;

    for (int kb = 0; kb <= kb_max; kb++) {
        if (kb < kb_max) {
            produce_kv(kb + 1);
            cp_commit();
            cp_wait1();
        } else {
            cp_wait0();
        }
        __syncthreads();

        const uint32_t kvbase = sb + FKV0 + (kb & 1) * KVBUF;

        // ---- QK^T ----
        float sc[8][4];
#pragma unroll
        for (int ni = 0; ni < 8; ni++)
#pragma unroll
            for (int q = 0; q < 4; q++) sc[ni][q] = 0.f;

#pragma unroll
        for (int ks = 0; ks < 4; ks++) {
            const uint32_t abyte = (wid * 16 + lr) * SASB + ks * 32 + lkb;
            uint32_t qh[4];
            ldmx4(qh, sb + abyte);
#pragma unroll
            for (int nb = 0; nb < 4; nb++) {
                const uint32_t bbyte = (nb * 16 + lr) * SASB + ks * 32 + lkb;
                uint32_t kh[4];
                ldmx4(kh, kvbase + bbyte);
                mma16816(sc[nb * 2],     qh, kh[0], kh[2]);
                mma16816(sc[nb * 2 + 1], qh, kh[1], kh[3]);
            }
        }

#pragma unroll
        for (int ni = 0; ni < 8; ni++)
#pragma unroll
            for (int q = 0; q < 4; q++) sc[ni][q] *= 0.125f;

        const int q0 = qb * 128 + wid * 16 + (lane >> 2);
        if (kb * 64 + 63 > qb * 128 + wid * 16) {
#pragma unroll
            for (int ni = 0; ni < 8; ni++) {
#pragma unroll
                for (int c = 0; c < 2; c++) {
                    const int col = kb * 64 + ni * 8 + (lane & 3) * 2 + c;
                    if (col > q0)     sc[ni][c]     = -1e30f;
                    if (col > q0 + 8) sc[ni][2 + c] = -1e30f;
                }
            }
        }

        float mx0 = -1e30f, mx1 = -1e30f;
#pragma unroll
        for (int ni = 0; ni < 8; ni++) {
            mx0 = fmaxf(mx0, fmaxf(sc[ni][0], sc[ni][1]));
            mx1 = fmaxf(mx1, fmaxf(sc[ni][2], sc[ni][3]));
        }
        mx0 = fmaxf(mx0, __shfl_xor_sync(0xffffffffu, mx0, 1));
        mx0 = fmaxf(mx0, __shfl_xor_sync(0xffffffffu, mx0, 2));
        mx1 = fmaxf(mx1, __shfl_xor_sync(0xffffffffu, mx1, 1));
        mx1 = fmaxf(mx1, __shfl_xor_sync(0xffffffffu, mx1, 2));

        const float mn0 = fmaxf(m0r, mx0);
        const float mn1 = fmaxf(m1r, mx1);
        const float al0 = __expf(m0r - mn0);
        const float al1 = __expf(m1r - mn1);
        m0r = mn0; m1r = mn1;

        float ls0 = 0.f, ls1 = 0.f;
#pragma unroll
        for (int ni = 0; ni < 8; ni++) {
            sc[ni][0] = __expf(sc[ni][0] - mn0); ls0 += sc[ni][0];
            sc[ni][1] = __expf(sc[ni][1] - mn0); ls0 += sc[ni][1];
            sc[ni][2] = __expf(sc[ni][2] - mn1); ls1 += sc[ni][2];
            sc[ni][3] = __expf(sc[ni][3] - mn1); ls1 += sc[ni][3];
        }
        ls0 += __shfl_xor_sync(0xffffffffu, ls0, 1);
        ls0 += __shfl_xor_sync(0xffffffffu, ls0, 2);
        ls1 += __shfl_xor_sync(0xffffffffu, ls1, 1);
        ls1 += __shfl_xor_sync(0xffffffffu, ls1, 2);
        l0r = l0r * al0 + ls0;
        l1r = l1r * al1 + ls1;
#pragma unroll
        for (int ni = 0; ni < 8; ni++) {
            o[ni][0] *= al0; o[ni][1] *= al0;
            o[ni][2] *= al1; o[ni][3] *= al1;
        }

        // ---- P.V ----
#pragma unroll
        for (int ks = 0; ks < 4; ks++) {
            uint32_t ph[4];
            ph[0] = packh(sc[2 * ks][0],     sc[2 * ks][1]);
            ph[1] = packh(sc[2 * ks][2],     sc[2 * ks][3]);
            ph[2] = packh(sc[2 * ks + 1][0], sc[2 * ks + 1][1]);
            ph[3] = packh(sc[2 * ks + 1][2], sc[2 * ks + 1][3]);
#pragma unroll
            for (int nt = 0; nt < 4; nt++) {
                const uint32_t vbyte =
                    (ks * 16 + ((lane >> 3) & 1) * 8 + (lane & 7)) * SASB +
                    nt * 32 + ((lane >> 4) << 4);
                uint32_t vh[4];
                ldmx4t(vh, kvbase + KVT + vbyte);
                mma16816(o[nt * 2],     ph, vh[0], vh[1]);
                mma16816(o[nt * 2 + 1], ph, vh[2], vh[3]);
            }
        }
        __syncthreads();
    }

    const float inv0 = 1.f / l0r;
    const float inv1 = 1.f / l1r;
    const int r0 = qb * 128 + wid * 16 + (lane >> 2);
    const int ec = (lane & 3) * 2;
#pragma unroll
    for (int ni = 0; ni < 8; ni++) {
        const size_t c = head + (size_t)ni * 8 + ec;
        *(uint32_t*)(Xv + c + (size_t)r0 * D_DIM) =
            packh(o[ni][0] * inv0, o[ni][1] * inv0);
        *(uint32_t*)(Xv + c + (size_t)(r0 + 8) * D_DIM) =
            packh(o[ni][2] * inv1, o[ni][3] * inv1);
    }
}

// ---------------------------------------------------------------------------
// launch
// ---------------------------------------------------------------------------
extern "C" void kernel_launch(void* const* d_in, const int* in_sizes, int n_in,
                              void* d_out, int out_size)
{
    const float* query = (const float*)d_in[0];
    const float* key   = (const float*)d_in[1];
    const float* value = (const float*)d_in[2];
    const float* Wq    = (const float*)d_in[3];
    const float* Wk    = (const float*)d_in[4];
    const float* Wv    = (const float*)d_in[5];
    const float* Wo    = (const float*)d_in[6];
    float* out = (float*)d_out;

    __half *aQ, *aK, *aV, *wq, *wk, *wv, *wo, *Qv, *Kv, *Vv, *Xv;
    cudaGetSymbolAddress((void**)&aQ, g_aQ); cudaGetSymbolAddress((void**)&aK, g_aK);
    cudaGetSymbolAddress((void**)&aV, g_aV);
    cudaGetSymbolAddress((void**)&wq, g_wq); cudaGetSymbolAddress((void**)&wk, g_wk);
    cudaGetSymbolAddress((void**)&wv, g_wv); cudaGetSymbolAddress((void**)&wo, g_wo);
    cudaGetSymbolAddress((void**)&Qv, g_Qv); cudaGetSymbolAddress((void**)&Kv, g_Kv);
    cudaGetSymbolAddress((void**)&Vv, g_Vv); cudaGetSymbolAddress((void**)&Xv, g_Xv);

    cudaFuncSetAttribute(gemm_proj, cudaFuncAttributeMaxDynamicSharedMemorySize,
                         SM_GEMM_TOTAL);
    cudaFuncSetAttribute(gemm_out, cudaFuncAttributeMaxDynamicSharedMemorySize,
                         SM_GEMM_TOTAL);
    cudaFuncSetAttribute(flash_mma, cudaFuncAttributeMaxDynamicSharedMemorySize,
                         FSM_TOTAL);

    dim3 cgrid(128, 1, 7);
    convert_all<<<cgrid, 256>>>((const float4*)query, (const float4*)key,
                                (const float4*)value, (const float4*)Wq,
                                (const float4*)Wk, (const float4*)Wv,
                                (const float4*)Wo,
                                (uint2*)aQ, (uint2*)aK, (uint2*)aV,
                                (uint2*)wq, (uint2*)wk, (uint2*)wv, (uint2*)wo);

    dim3 pgrid(D_DIM / 128, MTOT / 128, 3);   // (8, 32, 3)
    gemm_proj<<<pgrid, 256, SM_GEMM_TOTAL>>>(aQ, aK, aV, wq, wk, wv, Qv, Kv, Vv);

    dim3 fgrid(S_LEN / 128, H_NUM, B_SZ);     // (16, 16, 2)
    flash_mma<<<fgrid, 256, FSM_TOTAL>>>(Qv, Kv, Vv, Xv);

    dim3 ogrid(D_DIM / 128, MTOT / 128);      // (8, 32)
    gemm_out<<<ogrid, 256, SM_GEMM_TOTAL>>>(Xv, wo, out);
}